// round 12
// baseline (speedup 1.0000x reference)
#include <cuda_runtime.h>
#include <cuda_fp16.h>
#include <cstdint>

#define N_NODES 100000
#define N_EDGES 1200000
#define C_IN 64
#define C_HID 64
#define C_OUT 32

#define TB 256
#define GRID_E4 ((N_EDGES / 4 + TB - 1) / TB)      // 1172 (4 edges/thread)

#define T_TILE 64
#define GRID_T ((N_NODES + T_TILE - 1) / T_TILE)   // 1563

#define TILE_ITEMS 2048
#define N_TILES ((N_NODES + TILE_ITEMS - 1) / TILE_ITEMS)   // 49

// ---------------- scratch (device globals; zero-init at module load) --------
// State protocol: every launch leaves g_cursor / g_tstate / g_ticket zeroed
// for the next launch (k_fill re-zeros scan state, k_agg2 re-zeros cursor).
__device__ int     g_rowptr[N_NODES + 1];
__device__ int     g_cursor[N_NODES];
__device__ int     g_csrc[N_EDGES];
__device__ unsigned long long g_tstate[N_TILES];   // (status<<32)|value; 1=agg,2=prefix
__device__ int     g_ticket;
__device__ __half2 g_yh[N_NODES * 32];   // x @ W1_l   (fp16, gathered by agg1)
__device__ float   g_z [N_NODES * 64];   // x @ W1_r + b1
__device__ __half2 g_ph[N_NODES * 16];   // h @ W2_l   (fp16, gathered by agg2)
__device__ float   g_q [N_NODES * 32];   // h @ W2_r + b2

// ---------------- packed f32x2 helpers ----------------
__device__ __forceinline__ unsigned long long ffma2(unsigned long long a,
                                                    unsigned long long b,
                                                    unsigned long long c) {
    unsigned long long d;
    asm("fma.rn.f32x2 %0, %1, %2, %3;" : "=l"(d) : "l"(a), "l"(b), "l"(c));
    return d;
}
__device__ __forceinline__ unsigned long long packdup(float v) {
    unsigned long long r;
    asm("mov.b64 %0, {%1, %1};" : "=l"(r) : "f"(v));
    return r;
}
__device__ __forceinline__ float2 unpack2(unsigned long long v) {
    float2 r;
    asm("mov.b64 {%0, %1}, %2;" : "=f"(r.x), "=f"(r.y) : "l"(v));
    return r;
}

// ---------------- fused: tiled transform1 (blocks [0,GRID_T)) + count -------
__global__ void __launch_bounds__(TB, 3) k_count_t1(const int* __restrict__ ei,
                                                    const float* __restrict__ x,
                                                    const float* __restrict__ Wl,
                                                    const float* __restrict__ Wr,
                                                    const float* __restrict__ b1) {
    __shared__ __align__(16) float sX[64 * 64];    // [k][node]
    __shared__ __align__(16) float sW[64 * 128];   // [k][j] j<64: W1_l, else W1_r
    __shared__ float sB[64];

    int t = threadIdx.x;

    if (blockIdx.x >= GRID_T) {
        // ---- count branch: 4 edges/thread ----
        int i = (blockIdx.x - GRID_T) * TB + t;
        if (i < N_EDGES / 4) {
            int4 d4 = ((const int4*)(ei + N_EDGES))[i];
            if ((unsigned)d4.x < (unsigned)N_NODES) atomicAdd(&g_cursor[d4.x], 1);
            if ((unsigned)d4.y < (unsigned)N_NODES) atomicAdd(&g_cursor[d4.y], 1);
            if ((unsigned)d4.z < (unsigned)N_NODES) atomicAdd(&g_cursor[d4.z], 1);
            if ((unsigned)d4.w < (unsigned)N_NODES) atomicAdd(&g_cursor[d4.w], 1);
        }
        return;
    }

    int nbase = blockIdx.x * T_TILE;

    for (int idx = t; idx < 8192; idx += TB) {
        int k = idx >> 7, j = idx & 127;
        sW[idx] = (j < 64) ? Wl[k * 64 + j] : Wr[k * 64 + (j - 64)];
    }
    if (t < 64) sB[t] = b1[t];

    {
        int node = t & 63, kq = t >> 6;
        int ng = nbase + node;
        const float4* xr = (const float4*)(x + (size_t)ng * 64 + kq * 16);
        #pragma unroll
        for (int i = 0; i < 4; i++) {
            float4 v = (ng < N_NODES) ? xr[i] : make_float4(0.f, 0.f, 0.f, 0.f);
            int k0 = kq * 16 + i * 4;
            sX[(k0 + 0) * 64 + node] = v.x;
            sX[(k0 + 1) * 64 + node] = v.y;
            sX[(k0 + 2) * 64 + node] = v.z;
            sX[(k0 + 3) * 64 + node] = v.w;
        }
    }
    __syncthreads();

    int ty = t & 15;          // 4 nodes
    int tx = t >> 4;          // 8 outputs: j0 = 8*tx
    const float4*     sX4 = (const float4*)sX;       // row = 16 float4
    const ulonglong2* sWu = (const ulonglong2*)sW;   // row = 32 ulonglong2

    unsigned long long acc[16];
    #pragma unroll
    for (int i = 0; i < 16; i++) acc[i] = 0ull;

    float4     xc = sX4[ty];
    ulonglong2 wa = sWu[tx * 2 + 0];
    ulonglong2 wb = sWu[tx * 2 + 1];
    #pragma unroll 8
    for (int k = 0; k < 64; k++) {
        float4 xn; ulonglong2 wan, wbn;
        if (k < 63) {
            xn  = sX4[(k + 1) * 16 + ty];
            wan = sWu[(k + 1) * 32 + tx * 2 + 0];
            wbn = sWu[(k + 1) * 32 + tx * 2 + 1];
        }
        unsigned long long d0 = packdup(xc.x), d1 = packdup(xc.y);
        unsigned long long d2 = packdup(xc.z), d3 = packdup(xc.w);
        acc[0]  = ffma2(wa.x, d0, acc[0]);  acc[1]  = ffma2(wa.y, d0, acc[1]);
        acc[2]  = ffma2(wb.x, d0, acc[2]);  acc[3]  = ffma2(wb.y, d0, acc[3]);
        acc[4]  = ffma2(wa.x, d1, acc[4]);  acc[5]  = ffma2(wa.y, d1, acc[5]);
        acc[6]  = ffma2(wb.x, d1, acc[6]);  acc[7]  = ffma2(wb.y, d1, acc[7]);
        acc[8]  = ffma2(wa.x, d2, acc[8]);  acc[9]  = ffma2(wa.y, d2, acc[9]);
        acc[10] = ffma2(wb.x, d2, acc[10]); acc[11] = ffma2(wb.y, d2, acc[11]);
        acc[12] = ffma2(wa.x, d3, acc[12]); acc[13] = ffma2(wa.y, d3, acc[13]);
        acc[14] = ffma2(wb.x, d3, acc[14]); acc[15] = ffma2(wb.y, d3, acc[15]);
        xc = xn; wa = wan; wb = wbn;
    }

    int j0 = tx * 8;
    #pragma unroll
    for (int nn = 0; nn < 4; nn++) {
        int n = nbase + ty * 4 + nn;
        if (n >= N_NODES) break;
        const unsigned long long* a = acc + nn * 4;
        if (tx < 8) {
            __half2 hh[4];
            #pragma unroll
            for (int jp = 0; jp < 4; jp++) {
                float2 f = unpack2(a[jp]);
                hh[jp] = __floats2half2_rn(f.x, f.y);
            }
            *(uint4*)(g_yh + (size_t)n * 32 + (j0 >> 1)) = *(uint4*)hh;
        } else {
            float vz[8];
            #pragma unroll
            for (int jp = 0; jp < 4; jp++) {
                float2 f = unpack2(a[jp]);
                vz[2 * jp]     = f.x + sB[j0 - 64 + 2 * jp];
                vz[2 * jp + 1] = f.y + sB[j0 - 64 + 2 * jp + 1];
            }
            float4* dst = (float4*)(g_z + (size_t)n * 64 + (j0 - 64));
            dst[0] = *(float4*)(vz);
            dst[1] = *(float4*)(vz + 4);
        }
    }
}

// ---------------- single-pass scan: decoupled lookback ----------------
__global__ void __launch_bounds__(TB) k_scan() {
    __shared__ int s[2 * TB];
    __shared__ int stile;
    __shared__ int sprefix;
    int t = threadIdx.x;
    if (t == 0) stile = atomicAdd(&g_ticket, 1);
    __syncthreads();
    int tile = stile;
    int base = tile * TILE_ITEMS + t * 8;

    int v[8]; int sum = 0;
    #pragma unroll
    for (int i = 0; i < 8; i++) {
        int idx = base + i;
        v[i] = (idx < N_NODES) ? g_cursor[idx] : 0;
        sum += v[i];
    }
    s[t] = 0;
    int si = TB + t;
    s[si] = sum;
    __syncthreads();
    #pragma unroll
    for (int off = 1; off < TB; off <<= 1) {
        int x = s[si - off];
        __syncthreads();
        s[si] += x;
        __syncthreads();
    }
    int excl_thread = s[si] - sum;
    int block_total = s[2 * TB - 1];

    if (t == 0)
        atomicExch(&g_tstate[tile], (1ull << 32) | (unsigned)block_total);
    if (t < 32) {
        int prefix = 0;
        int b = tile;
        while (b > 0) {
            int look = b - 1 - t;
            unsigned long long st;
            if (look >= 0) {
                do { st = atomicAdd(&g_tstate[look], 0ull); } while ((st >> 32) == 0u);
            } else {
                st = (2ull << 32);
            }
            unsigned status = (unsigned)(st >> 32);
            int val = (int)(st & 0xffffffffu);
            unsigned pmask = __ballot_sync(0xffffffffu, status == 2u);
            int contrib;
            if (pmask) {
                int L = __ffs(pmask) - 1;
                contrib = (t <= L) ? val : 0;
            } else {
                contrib = val;
            }
            #pragma unroll
            for (int o = 16; o > 0; o >>= 1)
                contrib += __shfl_xor_sync(0xffffffffu, contrib, o);
            prefix += contrib;
            if (pmask) break;
            b -= 32;
        }
        if (t == 0) {
            sprefix = prefix;
            atomicExch(&g_tstate[tile],
                       (2ull << 32) | (unsigned)(prefix + block_total));
        }
    }
    __syncthreads();

    int pfx = sprefix + excl_thread;
    #pragma unroll
    for (int i = 0; i < 8; i++) {
        int idx = base + i;
        if (idx < N_NODES) { g_rowptr[idx] = pfx; g_cursor[idx] = pfx; }
        pfx += v[i];
        if (idx == N_NODES - 1) g_rowptr[N_NODES] = pfx;
    }
}

// ---------------- fill: 4 edges/thread; tail re-zeros scan state ------------
__global__ void k_fill(const int* __restrict__ ei) {
    int i = blockIdx.x * blockDim.x + threadIdx.x;
    if (i < N_EDGES / 4) {
        int4 s4 = ((const int4*)ei)[i];
        int4 d4 = ((const int4*)(ei + N_EDGES))[i];
        if ((unsigned)s4.x < (unsigned)N_NODES && (unsigned)d4.x < (unsigned)N_NODES) {
            int pos = atomicAdd(&g_cursor[d4.x], 1);
            if ((unsigned)pos < (unsigned)N_EDGES) g_csrc[pos] = s4.x;
        }
        if ((unsigned)s4.y < (unsigned)N_NODES && (unsigned)d4.y < (unsigned)N_NODES) {
            int pos = atomicAdd(&g_cursor[d4.y], 1);
            if ((unsigned)pos < (unsigned)N_EDGES) g_csrc[pos] = s4.y;
        }
        if ((unsigned)s4.z < (unsigned)N_NODES && (unsigned)d4.z < (unsigned)N_NODES) {
            int pos = atomicAdd(&g_cursor[d4.z], 1);
            if ((unsigned)pos < (unsigned)N_EDGES) g_csrc[pos] = s4.z;
        }
        if ((unsigned)s4.w < (unsigned)N_NODES && (unsigned)d4.w < (unsigned)N_NODES) {
            int pos = atomicAdd(&g_cursor[d4.w], 1);
            if ((unsigned)pos < (unsigned)N_EDGES) g_csrc[pos] = s4.w;
        }
    }
    // scan state already consumed this launch; zero it for the next launch
    if (blockIdx.x == 0) {
        if (threadIdx.x < N_TILES) g_tstate[threadIdx.x] = 0ull;
        if (threadIdx.x == N_TILES) g_ticket = 0;
    }
}

// ---------------- fused agg1 + transform2 -----------------------------------
// Phase A: 8 warps aggregate h for the block's 64 nodes (warp-per-node,
//   fp16 gather of g_yh, + z, relu) into sXrow[node][68] (padded rows).
// Phase B: transpose-stage sXrow -> sX[k][node], then the t2 GEMM.
__global__ void __launch_bounds__(TB, 3) k_agg1t2(const float* __restrict__ Wl,
                                                  const float* __restrict__ Wr,
                                                  const float* __restrict__ b2) {
    __shared__ __align__(16) float sXrow[64 * 68];  // [node][k], pad 68
    __shared__ __align__(16) float sX[64 * 64];     // [k][node]
    __shared__ __align__(16) float sW[64 * 64];     // [k][j] j<32: W2_l else W2_r
    __shared__ float sB[32];

    int t = threadIdx.x;
    int nbase = blockIdx.x * T_TILE;
    int wid = t >> 5, lane = t & 31;

    for (int idx = t; idx < 4096; idx += TB) {
        int k = idx >> 6, j = idx & 63;
        sW[idx] = (j < 32) ? Wl[k * 32 + j] : Wr[k * 32 + (j - 32)];
    }
    if (t < 32) sB[t] = b2[t];

    // ---- phase A: aggregate + relu -> sXrow ----
    #pragma unroll
    for (int r = 0; r < 8; r++) {
        int nl = r * 8 + wid;
        int n = nbase + nl;
        if (n < N_NODES) {
            int b = g_rowptr[n], eend = g_rowptr[n + 1];
            int deg = eend - b;
            float ax = 0.f, ay = 0.f;
            int e = b;
            for (; e + 8 <= eend; e += 8) {
                int s0 = g_csrc[e],     s1 = g_csrc[e + 1], s2 = g_csrc[e + 2], s3 = g_csrc[e + 3];
                int s4 = g_csrc[e + 4], s5 = g_csrc[e + 5], s6 = g_csrc[e + 6], s7 = g_csrc[e + 7];
                float2 f0 = __half22float2(g_yh[(size_t)s0 * 32 + lane]);
                float2 f1 = __half22float2(g_yh[(size_t)s1 * 32 + lane]);
                float2 f2 = __half22float2(g_yh[(size_t)s2 * 32 + lane]);
                float2 f3 = __half22float2(g_yh[(size_t)s3 * 32 + lane]);
                float2 f4 = __half22float2(g_yh[(size_t)s4 * 32 + lane]);
                float2 f5 = __half22float2(g_yh[(size_t)s5 * 32 + lane]);
                float2 f6 = __half22float2(g_yh[(size_t)s6 * 32 + lane]);
                float2 f7 = __half22float2(g_yh[(size_t)s7 * 32 + lane]);
                ax += ((f0.x + f1.x) + (f2.x + f3.x)) + ((f4.x + f5.x) + (f6.x + f7.x));
                ay += ((f0.y + f1.y) + (f2.y + f3.y)) + ((f4.y + f5.y) + (f6.y + f7.y));
            }
            if (e + 4 <= eend) {
                int s0 = g_csrc[e], s1 = g_csrc[e + 1], s2 = g_csrc[e + 2], s3 = g_csrc[e + 3];
                float2 f0 = __half22float2(g_yh[(size_t)s0 * 32 + lane]);
                float2 f1 = __half22float2(g_yh[(size_t)s1 * 32 + lane]);
                float2 f2 = __half22float2(g_yh[(size_t)s2 * 32 + lane]);
                float2 f3 = __half22float2(g_yh[(size_t)s3 * 32 + lane]);
                ax += (f0.x + f1.x) + (f2.x + f3.x);
                ay += (f0.y + f1.y) + (f2.y + f3.y);
                e += 4;
            }
            for (; e < eend; e++) {
                float2 f = __half22float2(g_yh[(size_t)g_csrc[e] * 32 + lane]);
                ax += f.x; ay += f.y;
            }
            float inv = 1.f / (float)(deg > 0 ? deg : 1);
            float2 z = *(const float2*)(g_z + (size_t)n * 64 + lane * 2);
            float2 h2;
            h2.x = fmaxf(fmaf(ax, inv, z.x), 0.f);
            h2.y = fmaxf(fmaf(ay, inv, z.y), 0.f);
            *(float2*)(sXrow + nl * 68 + lane * 2) = h2;
        }
    }
    __syncthreads();

    // ---- stage transpose sXrow -> sX[k][node] ----
    {
        int node = t & 63, kq = t >> 6;
        const float4* src = (const float4*)(sXrow + node * 68 + kq * 16);
        #pragma unroll
        for (int i = 0; i < 4; i++) {
            float4 v = src[i];
            int k0 = kq * 16 + i * 4;
            sX[(k0 + 0) * 64 + node] = v.x;
            sX[(k0 + 1) * 64 + node] = v.y;
            sX[(k0 + 2) * 64 + node] = v.z;
            sX[(k0 + 3) * 64 + node] = v.w;
        }
    }
    __syncthreads();

    // ---- phase B: GEMM (pipelined) ----
    int ty = t & 15;
    int tx = t >> 4;          // j0 = 4*tx
    const float4*     sX4 = (const float4*)sX;       // row = 16 float4
    const ulonglong2* sWu = (const ulonglong2*)sW;   // row = 16 ulonglong2

    unsigned long long acc[8];
    #pragma unroll
    for (int i = 0; i < 8; i++) acc[i] = 0ull;

    float4     xc = sX4[ty];
    ulonglong2 wa = sWu[tx];
    #pragma unroll 8
    for (int k = 0; k < 64; k++) {
        float4 xn; ulonglong2 wan;
        if (k < 63) {
            xn  = sX4[(k + 1) * 16 + ty];
            wan = sWu[(k + 1) * 16 + tx];
        }
        unsigned long long d0 = packdup(xc.x), d1 = packdup(xc.y);
        unsigned long long d2 = packdup(xc.z), d3 = packdup(xc.w);
        acc[0] = ffma2(wa.x, d0, acc[0]);  acc[1] = ffma2(wa.y, d0, acc[1]);
        acc[2] = ffma2(wa.x, d1, acc[2]);  acc[3] = ffma2(wa.y, d1, acc[3]);
        acc[4] = ffma2(wa.x, d2, acc[4]);  acc[5] = ffma2(wa.y, d2, acc[5]);
        acc[6] = ffma2(wa.x, d3, acc[6]);  acc[7] = ffma2(wa.y, d3, acc[7]);
        xc = xn; wa = wan;
    }

    int j0 = tx * 4;
    #pragma unroll
    for (int nn = 0; nn < 4; nn++) {
        int n = nbase + ty * 4 + nn;
        if (n >= N_NODES) break;
        const unsigned long long* a = acc + nn * 2;
        if (tx < 8) {
            float2 f0 = unpack2(a[0]);
            float2 f1 = unpack2(a[1]);
            __half2 hh[2] = { __floats2half2_rn(f0.x, f0.y),
                              __floats2half2_rn(f1.x, f1.y) };
            *(uint2*)(g_ph + (size_t)n * 16 + (j0 >> 1)) = *(uint2*)hh;
        } else {
            float2 f0 = unpack2(a[0]);
            float2 f1 = unpack2(a[1]);
            float4 vq = make_float4(f0.x + sB[j0 - 32], f0.y + sB[j0 - 31],
                                    f1.x + sB[j0 - 30], f1.y + sB[j0 - 29]);
            *(float4*)(g_q + (size_t)n * 32 + (j0 - 32)) = vq;
        }
    }
}

// ---------------- layer-2 aggregate -> output; tail re-zeros cursor ---------
__global__ void k_agg2(float* __restrict__ out) {
    // re-zero g_cursor for the next launch (cursor is dead after k_fill)
    {
        int i = blockIdx.x * blockDim.x + threadIdx.x;
        if (i < N_NODES) g_cursor[i] = 0;
    }
    int n = blockIdx.x * 8 + (threadIdx.x >> 5);
    if (n >= N_NODES) return;
    int lane = threadIdx.x & 31;
    int half = lane >> 4;
    int sub  = lane & 15;
    int b = g_rowptr[n], eend = g_rowptr[n + 1];
    int deg = eend - b;
    float ax = 0.f, ay = 0.f;
    int e = b;
    #pragma unroll 2
    for (; e + 2 <= eend; e += 2) {
        int s = g_csrc[e + half];
        float2 f = __half22float2(g_ph[(size_t)s * 16 + sub]);
        ax += f.x; ay += f.y;
    }
    if (e < eend && half == 0) {
        float2 f = __half22float2(g_ph[(size_t)g_csrc[e] * 16 + sub]);
        ax += f.x; ay += f.y;
    }
    ax += __shfl_xor_sync(0xffffffffu, ax, 16);
    ay += __shfl_xor_sync(0xffffffffu, ay, 16);
    if (half == 0) {
        float inv = 1.f / (float)(deg > 0 ? deg : 1);
        size_t o = (size_t)n * 32 + sub * 2;
        out[o]     = fmaf(ax, inv, g_q[o]);
        out[o + 1] = fmaf(ay, inv, g_q[o + 1]);
    }
}

// ---------------- launch ----------------
extern "C" void kernel_launch(void* const* d_in, const int* in_sizes, int n_in,
                              void* d_out, int out_size) {
    const float* x   = nullptr;
    const int*   ei  = nullptr;
    const float* W1l = nullptr;
    const float* W1r = nullptr;
    const float* b1  = nullptr;
    const float* W2l = nullptr;
    const float* W2r = nullptr;
    const float* b2  = nullptr;
    for (int i = 0; i < n_in; i++) {
        int sz = in_sizes[i];
        const void* p = d_in[i];
        if      (sz == N_NODES * C_IN)   x  = (const float*)p;
        else if (sz == 2 * N_EDGES)      ei = (const int*)p;
        else if (sz == C_IN * C_HID)   { if (!W1l) W1l = (const float*)p; else W1r = (const float*)p; }
        else if (sz == C_HID)            b1 = (const float*)p;
        else if (sz == C_HID * C_OUT)  { if (!W2l) W2l = (const float*)p; else W2r = (const float*)p; }
        else if (sz == C_OUT)            b2 = (const float*)p;
    }
    float* out = (float*)d_out;
    if (!x || !ei || !W1l || !W1r || !b1 || !W2l || !W2r || !b2) return;

    int gridW = (N_NODES + 7) / 8;             // 12500

    k_count_t1<<<GRID_T + GRID_E4, TB>>>(ei, x, W1l, W1r, b1);
    k_scan<<<N_TILES, TB>>>();
    k_fill<<<GRID_E4, TB>>>(ei);
    k_agg1t2<<<GRID_T, TB>>>(W2l, W2r, b2);
    k_agg2<<<gridW, TB>>>(out);
}